// round 7
// baseline (speedup 1.0000x reference)
#include <cuda_runtime.h>
#include <math.h>
#include <stdint.h>

// Problem constants
#define Bb   16
#define CIN  64
#define Hh   160
#define Ww   192
#define Nn   1000
#define AFC  16
#define Ss   96
#define Dd   2560          // AFC * H
#define HW   30720         // H * W
#define NCOLS 293

#define OUT_REG_ELEMS  ((size_t)Bb * Nn * NCOLS)
#define OUT_ATTN_ELEMS ((size_t)Bb * Nn * Nn)

// ---------------- scratch ----------------
__device__ float g_baf[(size_t)Bb * Nn * Dd];
__device__ float g_bafT[(size_t)Bb * Nn * Dd];
__device__ float g_att[(size_t)Bb * Nn * Dd];
__device__ float g_scores[(size_t)Bb * Nn * 1000];

// =============================== conv ======================================
__global__ __launch_bounds__(256)
void conv_kernel(const float* __restrict__ x, const float* __restrict__ w,
                 const float* __restrict__ bias, float* __restrict__ feats) {
    __shared__ float ws[AFC * CIN];
    __shared__ float bs[AFC];
    int tid = threadIdx.x;
    for (int t = tid; t < AFC * CIN; t += 256) ws[t] = w[t];
    if (tid < AFC) bs[tid] = bias[tid];
    __syncthreads();

    unsigned idx = blockIdx.x * 256u + tid;
    if (idx >= (unsigned)(Bb * (HW / 4))) return;
    int b = idx / (HW / 4);
    int q = idx % (HW / 4);
    size_t hw = (size_t)q * 4;

    const float* xp = x + (size_t)b * CIN * HW + hw;
    float4 acc[AFC];
#pragma unroll
    for (int o = 0; o < AFC; ++o) {
        float bv = bs[o];
        acc[o] = make_float4(bv, bv, bv, bv);
    }
#pragma unroll 4
    for (int c = 0; c < CIN; ++c) {
        float4 xv = *(const float4*)(xp + (size_t)c * HW);
#pragma unroll
        for (int o = 0; o < AFC; ++o) {
            float wv = ws[o * CIN + c];
            acc[o].x += xv.x * wv; acc[o].y += xv.y * wv;
            acc[o].z += xv.z * wv; acc[o].w += xv.w * wv;
        }
    }
    float* fp = feats + (size_t)b * AFC * HW + hw;
#pragma unroll
    for (int o = 0; o < AFC; ++o)
        *(float4*)(fp + (size_t)o * HW) = acc[o];
}

// =============================== gather ====================================
__global__ __launch_bounds__(256)
void gather_kernel(const float* __restrict__ feats, const int* __restrict__ cut_xs,
                   const unsigned* __restrict__ invalid, float* __restrict__ baf) {
    unsigned idx = blockIdx.x * 256u + threadIdx.x;
    int h = idx % Hh;
    unsigned r = idx / Hh;
    int a = r % AFC; r /= AFC;
    int n = r % Nn;
    int b = r / Nn;
    int xi = cut_xs[n * Hh + h];
    float v = 0.0f;
    if (invalid[n * Hh + h] == 0u)
        v = feats[(((size_t)b * AFC + a) * Hh + h) * Ww + xi];
    baf[(size_t)idx] = v;
}

// ============================ transpose baf -> bafT =========================
__global__ __launch_bounds__(256)
void transpose_kernel(const float* __restrict__ src, float* __restrict__ dst) {
    __shared__ float tile[32][33];
    int b = blockIdx.z;
    int n0 = blockIdx.y * 32, d0 = blockIdx.x * 32;
    const float* s = src + (size_t)b * Nn * Dd;
    float* dt = dst + (size_t)b * Nn * Dd;
    int tx = threadIdx.x, ty = threadIdx.y;
#pragma unroll
    for (int r = ty; r < 32; r += 8) {
        int n = n0 + r;
        tile[r][tx] = (n < Nn) ? s[(size_t)n * Dd + d0 + tx] : 0.0f;
    }
    __syncthreads();
#pragma unroll
    for (int r = ty; r < 32; r += 8) {
        int n = n0 + tx;
        if (n < Nn) dt[(size_t)(d0 + r) * Nn + n] = tile[tx][r];
    }
}

// ====================== tf32 warp-MMA GEMM (TN) =============================
// C[M,N] = A[M,K] * B[N,K]^T via mma.sync.m16n8k8.tf32.
// SMEM holds tf32 fragments in MMA register layout (conflict-free vector LDS).
// Block tile: 128 x 128, GBK=16. 8 warps as 2(M) x 4(N), warp tile 64 x 32.
// __launch_bounds__(256, 2) -> <=128 regs -> 2 CTAs/SM.
#define GBK 16

__device__ __forceinline__ uint32_t f2tf(float f) {
    uint32_t u;
    asm("cvt.rna.tf32.f32 %0, %1;" : "=r"(u) : "f"(f));
    return u;
}
__device__ __forceinline__ void mma_tf32(float* d, const uint32_t* a, const uint32_t* b) {
    asm volatile(
        "mma.sync.aligned.m16n8k8.row.col.f32.tf32.tf32.f32 "
        "{%0,%1,%2,%3}, {%4,%5,%6,%7}, {%8,%9}, {%0,%1,%2,%3};"
        : "+f"(d[0]), "+f"(d[1]), "+f"(d[2]), "+f"(d[3])
        : "r"(a[0]), "r"(a[1]), "r"(a[2]), "r"(a[3]), "r"(b[0]), "r"(b[1]));
}

__device__ __forceinline__ float4 ldA(const float* A1, const float* A2, int KA1, int lda,
                                      int M, int K, int bm, int row, int k) {
    int gr = bm + row;
    float4 v = make_float4(0.f, 0.f, 0.f, 0.f);
    if (gr < M && k < K) {
        const float* s = (k < KA1) ? A1 + (size_t)gr * lda + k
                                   : A2 + (size_t)gr * lda + (k - KA1);
        v = *(const float4*)s;
    }
    return v;
}
__device__ __forceinline__ float4 ldB(const float* B1, const float* B2, int NB1, int ldb,
                                      int N, int K, int bn, int row, int k) {
    int gn = bn + row;
    float4 v = make_float4(0.f, 0.f, 0.f, 0.f);
    if (gn < N && k < K) {
        const float* s = (gn < NB1) ? B1 + (size_t)gn * ldb + k
                                    : B2 + (size_t)(gn - NB1) * ldb + k;
        v = *(const float4*)s;
    }
    return v;
}

template<int EPI>
__device__ __forceinline__ void epi_store(float* __restrict__ C, int ldc, int M, int N,
                                          const float* __restrict__ bias1,
                                          const float* __restrict__ bias2,
                                          const float* __restrict__ anchors,
                                          int m, int n, float v) {
    if (m >= M || n >= N) return;
    if (EPI == 0) {
        C[(size_t)m * ldc + n] = v + bias1[n];
    } else if (EPI == 1) {
        C[(size_t)m * ldc + n] = v;
    } else {
        int nidx = m % Nn;
        if (n < 288) {
            v += bias1[n];
            if (n >= 192) v = 1.0f / (1.0f + expf(-v));
            v += anchors[(size_t)nidx * NCOLS + 5 + n];
            C[(size_t)m * ldc + 5 + n] = v;
        } else {
            C[(size_t)m * ldc + (n - 288)] = v + bias2[n - 288];
        }
    }
}

// Fragment layout:
// A element (row, k): tile=row>>4, lane=(row&7)*4+(k&3), slot=((k>>2)&1)*2+((row>>3)&1)
// B element (row, k): tile=row>>3, lane=(row&7)*4+(k&3), slot=(k>>2)&1
template<int EPI>
__global__ __launch_bounds__(256, 2)
void mma_gemm(const float* __restrict__ A1, const float* __restrict__ A2, int KA1, int lda,
              const float* __restrict__ B1, const float* __restrict__ B2, int NB1, int ldb,
              const float* __restrict__ bias1, const float* __restrict__ bias2,
              const float* __restrict__ anchors,
              float* __restrict__ C, int M, int N, int K, int ldc,
              size_t sA, size_t sB, size_t sC) {
    __shared__ uint32_t As[2][2][8][32][4];    // 16 KB
    __shared__ uint32_t Bs[2][2][16][32][2];   // 16 KB

    A1 += sA * blockIdx.z;
    A2 += sA * blockIdx.z;
    B1 += sB * blockIdx.z;
    C  += sC * blockIdx.z;
    int bm = blockIdx.y * 128;
    int bn = blockIdx.x * 128;

    int tid  = threadIdx.x;
    int wid  = tid >> 5, lane = tid & 31;
    int wm   = wid & 1;        // 2 warps along M: 64 rows
    int wn   = wid >> 1;       // 4 warps along N: 32 cols
    int lr   = lane >> 2;
    int lc   = lane & 3;

    float acc[4][4][4];
#pragma unroll
    for (int mi = 0; mi < 4; ++mi)
#pragma unroll
        for (int ni = 0; ni < 4; ++ni)
#pragma unroll
            for (int r = 0; r < 4; ++r) acc[mi][ni][r] = 0.0f;

    int nstages = (K + GBK - 1) / GBK;

    // ---- prologue: stage 0 -> buffer 0 ----
#pragma unroll
    for (int q = 0; q < 2; ++q) {
        int linear = tid + 256 * q;
        int row = linear >> 2, kq = linear & 3;
        {
            float4 v = ldA(A1, A2, KA1, lda, M, K, bm, row, kq * 4);
            int slot = (kq & 1) * 2 + ((row >> 3) & 1);
            uint32_t* p = &As[0][kq >> 1][row >> 4][(row & 7) * 4][slot];
            p[0] = f2tf(v.x); p[4] = f2tf(v.y); p[8] = f2tf(v.z); p[12] = f2tf(v.w);
        }
        {
            float4 v = ldB(B1, B2, NB1, ldb, N, K, bn, row, kq * 4);
            uint32_t* p = &Bs[0][kq >> 1][row >> 3][(row & 7) * 4][kq & 1];
            p[0] = f2tf(v.x); p[2] = f2tf(v.y); p[4] = f2tf(v.z); p[6] = f2tf(v.w);
        }
    }
    __syncthreads();

    for (int i = 0; i < nstages; ++i) {
        int cur = i & 1;
        // ---- prefetch next stage into registers ----
        float4 pA[2], pB[2];
        if (i + 1 < nstages) {
            int k0 = (i + 1) * GBK;
#pragma unroll
            for (int q = 0; q < 2; ++q) {
                int linear = tid + 256 * q;
                pA[q] = ldA(A1, A2, KA1, lda, M, K, bm, linear >> 2, k0 + (linear & 3) * 4);
                pB[q] = ldB(B1, B2, NB1, ldb, N, K, bn, linear >> 2, k0 + (linear & 3) * 4);
            }
        }
        // ---- compute: vector LDS + HMMA only ----
#pragma unroll
        for (int ks = 0; ks < 2; ++ks) {
            uint4 af[4];
            uint2 bf[4];
#pragma unroll
            for (int mi = 0; mi < 4; ++mi)
                af[mi] = *(const uint4*)&As[cur][ks][wm * 4 + mi][lane][0];
#pragma unroll
            for (int ni = 0; ni < 4; ++ni)
                bf[ni] = *(const uint2*)&Bs[cur][ks][wn * 4 + ni][lane][0];
#pragma unroll
            for (int mi = 0; mi < 4; ++mi)
#pragma unroll
                for (int ni = 0; ni < 4; ++ni)
                    mma_tf32(acc[mi][ni], (const uint32_t*)&af[mi], (const uint32_t*)&bf[ni]);
        }
        // ---- commit prefetch into other buffer ----
        if (i + 1 < nstages) {
            int nxt = cur ^ 1;
            __syncthreads();
#pragma unroll
            for (int q = 0; q < 2; ++q) {
                int linear = tid + 256 * q;
                int row = linear >> 2, kq = linear & 3;
                int slot = (kq & 1) * 2 + ((row >> 3) & 1);
                uint32_t* pa = &As[nxt][kq >> 1][row >> 4][(row & 7) * 4][slot];
                pa[0] = f2tf(pA[q].x); pa[4] = f2tf(pA[q].y);
                pa[8] = f2tf(pA[q].z); pa[12] = f2tf(pA[q].w);
                uint32_t* pb = &Bs[nxt][kq >> 1][row >> 3][(row & 7) * 4][kq & 1];
                pb[0] = f2tf(pB[q].x); pb[2] = f2tf(pB[q].y);
                pb[4] = f2tf(pB[q].z); pb[6] = f2tf(pB[q].w);
            }
            __syncthreads();
        }
    }

    // ---- epilogue ----
#pragma unroll
    for (int mi = 0; mi < 4; ++mi) {
#pragma unroll
        for (int ni = 0; ni < 4; ++ni) {
            float* d = acc[mi][ni];
            int mb = bm + wm * 64 + mi * 16 + lr;
            int nb = bn + wn * 32 + ni * 8 + lc * 2;
            epi_store<EPI>(C, ldc, M, N, bias1, bias2, anchors, mb,     nb,     d[0]);
            epi_store<EPI>(C, ldc, M, N, bias1, bias2, anchors, mb,     nb + 1, d[1]);
            epi_store<EPI>(C, ldc, M, N, bias1, bias2, anchors, mb + 8, nb,     d[2]);
            epi_store<EPI>(C, ldc, M, N, bias1, bias2, anchors, mb + 8, nb + 1, d[3]);
        }
    }
}

// =============================== softmax ====================================
__global__ __launch_bounds__(256)
void softmax_kernel(const float* __restrict__ scores, float* __restrict__ attn_out) {
    __shared__ float red[256];
    int m = blockIdx.x;
    int i = m % Nn;
    int t = threadIdx.x;
    const float* row = scores + (size_t)m * 1000;

    float v[4];
    float mx = -INFINITY;
#pragma unroll
    for (int r = 0; r < 4; ++r) {
        int j = t + r * 256;
        v[r] = (j < Nn - 1) ? row[j] : -INFINITY;
        mx = fmaxf(mx, v[r]);
    }
    red[t] = mx;
    __syncthreads();
    for (int s = 128; s > 0; s >>= 1) {
        if (t < s) red[t] = fmaxf(red[t], red[t + s]);
        __syncthreads();
    }
    mx = red[0];
    __syncthreads();

    float sum = 0.0f;
#pragma unroll
    for (int r = 0; r < 4; ++r) {
        int j = t + r * 256;
        v[r] = (j < Nn - 1) ? __expf(v[r] - mx) : 0.0f;
        sum += v[r];
    }
    red[t] = sum;
    __syncthreads();
    for (int s = 128; s > 0; s >>= 1) {
        if (t < s) red[t] += red[t + s];
        __syncthreads();
    }
    float inv = 1.0f / red[0];

    float* out = attn_out + (size_t)m * Nn;
#pragma unroll
    for (int r = 0; r < 4; ++r) {
        int j = t + r * 256;
        if (j < Nn - 1) {
            int pos = j + (j >= i);
            out[pos] = v[r] * inv;
        }
    }
    if (t == 0) out[i] = 0.0f;
}

// ============================ anchors passthrough ===========================
__global__ void anchor_kernel(const float* __restrict__ anchors, float* __restrict__ out) {
    int idx = blockIdx.x * blockDim.x + threadIdx.x;
    if (idx >= Bb * Nn * 3) return;
    int m = idx / 3, t = idx % 3;
    out[(size_t)m * NCOLS + 2 + t] = anchors[(size_t)(m % Nn) * NCOLS + 2 + t];
}

// ===========================================================================
extern "C" void kernel_launch(void* const* d_in, const int* in_sizes, int n_in,
                              void* d_out, int out_size) {
    const float*    x       = (const float*)d_in[0];
    const float*    conv_w  = (const float*)d_in[1];
    const float*    conv_b  = (const float*)d_in[2];
    const int*      cut_xs  = (const int*)d_in[3];
    const unsigned* invalid = (const unsigned*)d_in[4];
    const float*    anchors = (const float*)d_in[5];
    const float*    attn_w  = (const float*)d_in[6];
    const float*    attn_b  = (const float*)d_in[7];
    const float*    cls_w   = (const float*)d_in[8];
    const float*    cls_b   = (const float*)d_in[9];
    const float*    reg_w   = (const float*)d_in[10];
    const float*    reg_b   = (const float*)d_in[11];

    float* out       = (float*)d_out;
    float* out_reg   = out;
    float* out_attn  = out + OUT_REG_ELEMS;
    float* out_feats = out_attn + OUT_ATTN_ELEMS;

    float *baf, *bafT, *att, *scores;
    cudaGetSymbolAddress((void**)&baf, g_baf);
    cudaGetSymbolAddress((void**)&bafT, g_bafT);
    cudaGetSymbolAddress((void**)&att, g_att);
    cudaGetSymbolAddress((void**)&scores, g_scores);

    // 1) 1x1 conv -> feats (in d_out)
    conv_kernel<<<480, 256>>>(x, conv_w, conv_b, out_feats);

    // 2) ROI gather -> baf
    gather_kernel<<<160000, 256>>>(out_feats, cut_xs, invalid, baf);

    // 3) bafT[b][d][n] = baf[b][n][d]
    transpose_kernel<<<dim3(Dd / 32, 32, Bb), dim3(32, 8)>>>(baf, bafT);

    // 4) scores = baf @ attn_w^T + attn_b   (M=16000 N=999 K=2560)
    mma_gemm<0><<<dim3(8, 125, 1), 256>>>(
        baf, baf, Dd, Dd, attn_w, attn_w, Nn - 1, Dd,
        attn_b, nullptr, nullptr,
        scores, Bb * Nn, Nn - 1, Dd, 1000, 0, 0, 0);

    // 5) softmax + diagonal-zero scatter -> attn_mat (in d_out)
    softmax_kernel<<<Bb * Nn, 256>>>(scores, out_attn);

    // 6) att = attn_mat @ bafT^T (per batch: M=1000 N=2560 K=1000)
    mma_gemm<1><<<dim3(20, 8, Bb), 256>>>(
        out_attn, out_attn, Nn, Nn, bafT, bafT, Dd, Nn,
        nullptr, nullptr, nullptr,
        att, Nn, Dd, Nn, Dd,
        (size_t)Nn * Nn, (size_t)Nn * Dd, (size_t)Nn * Dd);

    // 7) fused reg+cls GEMM over concat A=[att|baf] (M=16000 N=290 K=5120)
    mma_gemm<2><<<dim3(3, 125, 1), 256>>>(
        att, baf, Dd, Dd, reg_w, cls_w, 3 * Ss, 2 * Dd,
        reg_b, cls_b, anchors,
        out_reg, Bb * Nn, 3 * Ss + 2, 2 * Dd, NCOLS, 0, 0, 0);

    // 8) anchors[:, 2:5] passthrough
    anchor_kernel<<<(Bb * Nn * 3 + 255) / 256, 256>>>(anchors, out_reg);
}

// round 8
// speedup vs baseline: 1.4261x; 1.4261x over previous
#include <cuda_runtime.h>
#include <math.h>
#include <stdint.h>

// Problem constants
#define Bb   16
#define CIN  64
#define Hh   160
#define Ww   192
#define Nn   1000
#define AFC  16
#define Ss   96
#define Dd   2560          // AFC * H
#define HW   30720         // H * W
#define NCOLS 293

#define OUT_REG_ELEMS  ((size_t)Bb * Nn * NCOLS)
#define OUT_ATTN_ELEMS ((size_t)Bb * Nn * Nn)

// ---------------- scratch ----------------
__device__ float g_baf[(size_t)Bb * Nn * Dd];
__device__ float g_bafT[(size_t)Bb * Nn * Dd];
__device__ float g_att[(size_t)Bb * Nn * Dd];
__device__ float g_scores[(size_t)Bb * Nn * 1000];

// =============================== conv ======================================
__global__ __launch_bounds__(256)
void conv_kernel(const float* __restrict__ x, const float* __restrict__ w,
                 const float* __restrict__ bias, float* __restrict__ feats) {
    __shared__ float ws[AFC * CIN];
    __shared__ float bs[AFC];
    int tid = threadIdx.x;
    for (int t = tid; t < AFC * CIN; t += 256) ws[t] = w[t];
    if (tid < AFC) bs[tid] = bias[tid];
    __syncthreads();

    unsigned idx = blockIdx.x * 256u + tid;
    if (idx >= (unsigned)(Bb * (HW / 4))) return;
    int b = idx / (HW / 4);
    int q = idx % (HW / 4);
    size_t hw = (size_t)q * 4;

    const float* xp = x + (size_t)b * CIN * HW + hw;
    float4 acc[AFC];
#pragma unroll
    for (int o = 0; o < AFC; ++o) {
        float bv = bs[o];
        acc[o] = make_float4(bv, bv, bv, bv);
    }
#pragma unroll 4
    for (int c = 0; c < CIN; ++c) {
        float4 xv = *(const float4*)(xp + (size_t)c * HW);
#pragma unroll
        for (int o = 0; o < AFC; ++o) {
            float wv = ws[o * CIN + c];
            acc[o].x += xv.x * wv; acc[o].y += xv.y * wv;
            acc[o].z += xv.z * wv; acc[o].w += xv.w * wv;
        }
    }
    float* fp = feats + (size_t)b * AFC * HW + hw;
#pragma unroll
    for (int o = 0; o < AFC; ++o)
        *(float4*)(fp + (size_t)o * HW) = acc[o];
}

// =============================== gather ====================================
__global__ __launch_bounds__(256)
void gather_kernel(const float* __restrict__ feats, const int* __restrict__ cut_xs,
                   const unsigned* __restrict__ invalid, float* __restrict__ baf) {
    unsigned idx = blockIdx.x * 256u + threadIdx.x;
    int h = idx % Hh;
    unsigned r = idx / Hh;
    int a = r % AFC; r /= AFC;
    int n = r % Nn;
    int b = r / Nn;
    int xi = cut_xs[n * Hh + h];
    float v = 0.0f;
    if (invalid[n * Hh + h] == 0u)
        v = feats[(((size_t)b * AFC + a) * Hh + h) * Ww + xi];
    baf[(size_t)idx] = v;
}

// ============================ transpose baf -> bafT =========================
__global__ __launch_bounds__(256)
void transpose_kernel(const float* __restrict__ src, float* __restrict__ dst) {
    __shared__ float tile[32][33];
    int b = blockIdx.z;
    int n0 = blockIdx.y * 32, d0 = blockIdx.x * 32;
    const float* s = src + (size_t)b * Nn * Dd;
    float* dt = dst + (size_t)b * Nn * Dd;
    int tx = threadIdx.x, ty = threadIdx.y;
#pragma unroll
    for (int r = ty; r < 32; r += 8) {
        int n = n0 + r;
        tile[r][tx] = (n < Nn) ? s[(size_t)n * Dd + d0 + tx] : 0.0f;
    }
    __syncthreads();
#pragma unroll
    for (int r = ty; r < 32; r += 8) {
        int n = n0 + tx;
        if (n < Nn) dt[(size_t)(d0 + r) * Nn + n] = tile[tx][r];
    }
}

// ====================== tf32 warp-MMA GEMM (TN), cp.async ===================
// C[M,N] = A[M,K] * B[N,K]^T via mma.sync.m16n8k8.tf32 on RAW fp32 operands
// (HW truncates to tf32; no cvt anywhere).
// 128 threads, 4 warps as 2(M) x 2(N), warp tile 64x64, block tile 128x128.
// SMEM: [row][k] raw fp32, row stride 20 words (GBK 16 + pad 4) -> LDS addr
// lr*20+lc covers all 32 banks (conflict-free). 3-stage cp.async ring.
#define GBK     16
#define RSTRIDE 20                       // words per row
#define TILE_W  (128 * RSTRIDE)          // words per operand tile (2560)
#define STAGE_W (2 * TILE_W)             // words per stage (A then B)
#define NSTAGE  3
#define GEMM_SMEM_BYTES (NSTAGE * STAGE_W * 4)   // 61440

__device__ __forceinline__ uint32_t smem_u32(const void* p) {
    uint32_t a;
    asm("{ .reg .u64 t; cvta.to.shared.u64 t, %1; cvt.u32.u64 %0, t; }" : "=r"(a) : "l"(p));
    return a;
}
__device__ __forceinline__ void cp16(uint32_t dst, const float* src, int sz) {
    asm volatile("cp.async.cg.shared.global [%0], [%1], 16, %2;"
                 :: "r"(dst), "l"(src), "r"(sz));
}
__device__ __forceinline__ void mma_tf32(float* d, const uint32_t* a, const uint32_t* b) {
    asm volatile(
        "mma.sync.aligned.m16n8k8.row.col.f32.tf32.tf32.f32 "
        "{%0,%1,%2,%3}, {%4,%5,%6,%7}, {%8,%9}, {%0,%1,%2,%3};"
        : "+f"(d[0]), "+f"(d[1]), "+f"(d[2]), "+f"(d[3])
        : "r"(a[0]), "r"(a[1]), "r"(a[2]), "r"(a[3]), "r"(b[0]), "r"(b[1]));
}

template<int EPI>
__device__ __forceinline__ void epi_store(float* __restrict__ C, int ldc, int M, int N,
                                          const float* __restrict__ bias1,
                                          const float* __restrict__ bias2,
                                          const float* __restrict__ anchors,
                                          int m, int n, float v) {
    if (m >= M || n >= N) return;
    if (EPI == 0) {
        C[(size_t)m * ldc + n] = v + bias1[n];
    } else if (EPI == 1) {
        C[(size_t)m * ldc + n] = v;
    } else {
        int nidx = m % Nn;
        if (n < 288) {
            v += bias1[n];
            if (n >= 192) v = 1.0f / (1.0f + expf(-v));
            v += anchors[(size_t)nidx * NCOLS + 5 + n];
            C[(size_t)m * ldc + 5 + n] = v;
        } else {
            C[(size_t)m * ldc + (n - 288)] = v + bias2[n - 288];
        }
    }
}

template<int EPI>
__global__ __launch_bounds__(128, 2)
void mma_gemm(const float* __restrict__ A1, const float* __restrict__ A2, int KA1, int lda,
              const float* __restrict__ B1, const float* __restrict__ B2, int NB1, int ldb,
              const float* __restrict__ bias1, const float* __restrict__ bias2,
              const float* __restrict__ anchors,
              float* __restrict__ C, int M, int N, int K, int ldc,
              size_t sA, size_t sB, size_t sC) {
    extern __shared__ float smem[];
    uint32_t sbase = smem_u32(smem);

    A1 += sA * blockIdx.z;
    A2 += sA * blockIdx.z;
    B1 += sB * blockIdx.z;
    C  += sC * blockIdx.z;
    int bm = blockIdx.y * 128;
    int bn = blockIdx.x * 128;

    int tid  = threadIdx.x;
    int wid  = tid >> 5, lane = tid & 31;
    int wm   = wid & 1;        // 2 warps along M: 64 rows
    int wn   = wid >> 1;       // 2 warps along N: 64 cols
    int lr   = lane >> 2;
    int lc   = lane & 3;

    int nstages = (K + GBK - 1) / GBK;

    // ---- stage issue: 8 cp.async 16B chunks per thread ----
    auto issue_stage = [&](int stg, int k0) {
        uint32_t soff = sbase + ((stg % NSTAGE) * STAGE_W) * 4;
#pragma unroll
        for (int q = 0; q < 4; ++q) {
            int linear = tid + 128 * q;         // 0..511
            int row = linear >> 2;
            int c   = linear & 3;
            int k   = k0 + c * 4;
            // A chunk
            {
                int gr = bm + row;
                const float* p = A1;
                int sz = 0;
                if (gr < M && k < K) {
                    p = (k < KA1) ? A1 + (size_t)gr * lda + k
                                  : A2 + (size_t)gr * lda + (k - KA1);
                    sz = 16;
                }
                cp16(soff + (row * RSTRIDE + c * 4) * 4, p, sz);
            }
            // B chunk
            {
                int gn = bn + row;
                const float* p = B1;
                int sz = 0;
                if (gn < N && k < K) {
                    p = (gn < NB1) ? B1 + (size_t)gn * ldb + k
                                   : B2 + (size_t)(gn - NB1) * ldb + k;
                    sz = 16;
                }
                cp16(soff + (TILE_W + row * RSTRIDE + c * 4) * 4, p, sz);
            }
        }
        asm volatile("cp.async.commit_group;" ::: "memory");
    };

    float acc[4][8][4];
#pragma unroll
    for (int mi = 0; mi < 4; ++mi)
#pragma unroll
        for (int ni = 0; ni < 8; ++ni)
#pragma unroll
            for (int r = 0; r < 4; ++r) acc[mi][ni][r] = 0.0f;

    // ---- prologue: stages 0, 1 ----
    issue_stage(0, 0);
    issue_stage(1, GBK);

    for (int i = 0; i < nstages; ++i) {
        asm volatile("cp.async.wait_group 1;" ::: "memory");
        __syncthreads();

        // issue stage i+2 into the buffer consumed in iteration i-1
        if (i + 2 < nstages) {
            issue_stage(i + 2, (i + 2) * GBK);
        } else {
            asm volatile("cp.async.commit_group;" ::: "memory");  // keep group count uniform
        }

        // ---- compute stage i ----
        const float* sa = smem + (i % NSTAGE) * STAGE_W;
        const float* sb = sa + TILE_W;
#pragma unroll
        for (int ks = 0; ks < 2; ++ks) {
            int kk = ks * 8;
            uint32_t af[4][4], bf[8][2];
#pragma unroll
            for (int mi = 0; mi < 4; ++mi) {
                int m = wm * 64 + mi * 16 + lr;
                const float* r0 = sa + m * RSTRIDE + kk;
                const float* r1 = sa + (m + 8) * RSTRIDE + kk;
                af[mi][0] = __float_as_uint(r0[lc]);
                af[mi][1] = __float_as_uint(r1[lc]);
                af[mi][2] = __float_as_uint(r0[lc + 4]);
                af[mi][3] = __float_as_uint(r1[lc + 4]);
            }
#pragma unroll
            for (int ni = 0; ni < 8; ++ni) {
                int n = wn * 64 + ni * 8 + lr;
                const float* r0 = sb + n * RSTRIDE + kk;
                bf[ni][0] = __float_as_uint(r0[lc]);
                bf[ni][1] = __float_as_uint(r0[lc + 4]);
            }
#pragma unroll
            for (int mi = 0; mi < 4; ++mi)
#pragma unroll
                for (int ni = 0; ni < 8; ++ni)
                    mma_tf32(acc[mi][ni], af[mi], bf[ni]);
        }
        __syncthreads();
    }

    // ---- epilogue ----
#pragma unroll
    for (int mi = 0; mi < 4; ++mi) {
#pragma unroll
        for (int ni = 0; ni < 8; ++ni) {
            float* d = acc[mi][ni];
            int mb = bm + wm * 64 + mi * 16 + lr;
            int nb = bn + wn * 64 + ni * 8 + lc * 2;
            epi_store<EPI>(C, ldc, M, N, bias1, bias2, anchors, mb,     nb,     d[0]);
            epi_store<EPI>(C, ldc, M, N, bias1, bias2, anchors, mb,     nb + 1, d[1]);
            epi_store<EPI>(C, ldc, M, N, bias1, bias2, anchors, mb + 8, nb,     d[2]);
            epi_store<EPI>(C, ldc, M, N, bias1, bias2, anchors, mb + 8, nb + 1, d[3]);
        }
    }
}

// =============================== softmax ====================================
__global__ __launch_bounds__(256)
void softmax_kernel(const float* __restrict__ scores, float* __restrict__ attn_out) {
    __shared__ float red[256];
    int m = blockIdx.x;
    int i = m % Nn;
    int t = threadIdx.x;
    const float* row = scores + (size_t)m * 1000;

    float v[4];
    float mx = -INFINITY;
#pragma unroll
    for (int r = 0; r < 4; ++r) {
        int j = t + r * 256;
        v[r] = (j < Nn - 1) ? row[j] : -INFINITY;
        mx = fmaxf(mx, v[r]);
    }
    red[t] = mx;
    __syncthreads();
    for (int s = 128; s > 0; s >>= 1) {
        if (t < s) red[t] = fmaxf(red[t], red[t + s]);
        __syncthreads();
    }
    mx = red[0];
    __syncthreads();

    float sum = 0.0f;
#pragma unroll
    for (int r = 0; r < 4; ++r) {
        int j = t + r * 256;
        v[r] = (j < Nn - 1) ? __expf(v[r] - mx) : 0.0f;
        sum += v[r];
    }
    red[t] = sum;
    __syncthreads();
    for (int s = 128; s > 0; s >>= 1) {
        if (t < s) red[t] += red[t + s];
        __syncthreads();
    }
    float inv = 1.0f / red[0];

    float* out = attn_out + (size_t)m * Nn;
#pragma unroll
    for (int r = 0; r < 4; ++r) {
        int j = t + r * 256;
        if (j < Nn - 1) {
            int pos = j + (j >= i);
            out[pos] = v[r] * inv;
        }
    }
    if (t == 0) out[i] = 0.0f;
}

// ============================ anchors passthrough ===========================
__global__ void anchor_kernel(const float* __restrict__ anchors, float* __restrict__ out) {
    int idx = blockIdx.x * blockDim.x + threadIdx.x;
    if (idx >= Bb * Nn * 3) return;
    int m = idx / 3, t = idx % 3;
    out[(size_t)m * NCOLS + 2 + t] = anchors[(size_t)(m % Nn) * NCOLS + 2 + t];
}

// ===========================================================================
extern "C" void kernel_launch(void* const* d_in, const int* in_sizes, int n_in,
                              void* d_out, int out_size) {
    const float*    x       = (const float*)d_in[0];
    const float*    conv_w  = (const float*)d_in[1];
    const float*    conv_b  = (const float*)d_in[2];
    const int*      cut_xs  = (const int*)d_in[3];
    const unsigned* invalid = (const unsigned*)d_in[4];
    const float*    anchors = (const float*)d_in[5];
    const float*    attn_w  = (const float*)d_in[6];
    const float*    attn_b  = (const float*)d_in[7];
    const float*    cls_w   = (const float*)d_in[8];
    const float*    cls_b   = (const float*)d_in[9];
    const float*    reg_w   = (const float*)d_in[10];
    const float*    reg_b   = (const float*)d_in[11];

    float* out       = (float*)d_out;
    float* out_reg   = out;
    float* out_attn  = out + OUT_REG_ELEMS;
    float* out_feats = out_attn + OUT_ATTN_ELEMS;

    float *baf, *bafT, *att, *scores;
    cudaGetSymbolAddress((void**)&baf, g_baf);
    cudaGetSymbolAddress((void**)&bafT, g_bafT);
    cudaGetSymbolAddress((void**)&att, g_att);
    cudaGetSymbolAddress((void**)&scores, g_scores);

    cudaFuncSetAttribute(mma_gemm<0>, cudaFuncAttributeMaxDynamicSharedMemorySize, GEMM_SMEM_BYTES);
    cudaFuncSetAttribute(mma_gemm<1>, cudaFuncAttributeMaxDynamicSharedMemorySize, GEMM_SMEM_BYTES);
    cudaFuncSetAttribute(mma_gemm<2>, cudaFuncAttributeMaxDynamicSharedMemorySize, GEMM_SMEM_BYTES);

    // 1) 1x1 conv -> feats (in d_out)
    conv_kernel<<<480, 256>>>(x, conv_w, conv_b, out_feats);

    // 2) ROI gather -> baf
    gather_kernel<<<160000, 256>>>(out_feats, cut_xs, invalid, baf);

    // 3) bafT[b][d][n] = baf[b][n][d]
    transpose_kernel<<<dim3(Dd / 32, 32, Bb), dim3(32, 8)>>>(baf, bafT);

    // 4) scores = baf @ attn_w^T + attn_b   (M=16000 N=999 K=2560)
    mma_gemm<0><<<dim3(8, 125, 1), 128, GEMM_SMEM_BYTES>>>(
        baf, baf, Dd, Dd, attn_w, attn_w, Nn - 1, Dd,
        attn_b, nullptr, nullptr,
        scores, Bb * Nn, Nn - 1, Dd, 1000, 0, 0, 0);

    // 5) softmax + diagonal-zero scatter -> attn_mat (in d_out)
    softmax_kernel<<<Bb * Nn, 256>>>(scores, out_attn);

    // 6) att = attn_mat @ bafT^T (per batch: M=1000 N=2560 K=1000)
    mma_gemm<1><<<dim3(20, 8, Bb), 128, GEMM_SMEM_BYTES>>>(
        out_attn, out_attn, Nn, Nn, bafT, bafT, Dd, Nn,
        nullptr, nullptr, nullptr,
        att, Nn, Dd, Nn, Dd,
        (size_t)Nn * Nn, (size_t)Nn * Dd, (size_t)Nn * Dd);

    // 7) fused reg+cls GEMM over concat A=[att|baf] (M=16000 N=290 K=5120)
    mma_gemm<2><<<dim3(3, 125, 1), 128, GEMM_SMEM_BYTES>>>(
        att, baf, Dd, Dd, reg_w, cls_w, 3 * Ss, 2 * Dd,
        reg_b, cls_b, anchors,
        out_reg, Bb * Nn, 3 * Ss + 2, 2 * Dd, NCOLS, 0, 0, 0);

    // 8) anchors[:, 2:5] passthrough
    anchor_kernel<<<(Bb * Nn * 3 + 255) / 256, 256>>>(anchors, out_reg);
}